// round 4
// baseline (speedup 1.0000x reference)
#include <cuda_runtime.h>

// NeuralODE dopri5 rollout — fp32x2 packed SIMT persistent kernel, v3.
// v3: W1 packed float4 (LDG.128), software-pipelined weight prefetch in
// layer 1, LDS.128 weights in layer 2.

#define NT 256
#define MT 16
#define NBLK 128
#define DIM 64
#define WID 256
#define BD (2048*64)

// shared memory layout (float offsets)
#define OFF_W0 0            // 256 x 68 (pad, 16B-aligned rows) = 17408
#define OFF_W2 17408        // 64 x 264 (pad, 16B-aligned rows) = 16896
#define OFF_B0 34304
#define OFF_B1 34560
#define OFF_B2 34816
#define OFF_Y  34880        // paired [8][64] float2 = 1024 floats
#define OFF_YS 35904        // 1024
#define OFF_H1 36928        // paired [8][256] float2 = 4096
#define OFF_H2 41024        // 4096
#define OFF_K  45120        // 6 x 1024
#define SMEM_FLOATS 51264
#define SMEM_BYTES (SMEM_FLOATS * 4)

typedef unsigned long long u64;

// W1 packed: g_W1P[kk*256 + j] = {W1[j][4kk], W1[j][4kk+1], W1[j][4kk+2], W1[j][4kk+3]}
__device__ float4 g_W1P[64 * WID];

__global__ void pack_w1(const float* __restrict__ w1) {
    int idx = blockIdx.x * 256 + threadIdx.x;   // 0..16383
    int kk = idx >> 8;
    int j = idx & 255;
    float4 v = *(const float4*)(w1 + j * WID + kk * 4);
    g_W1P[kk * WID + j] = v;
}

__device__ __forceinline__ u64 pack2(float w) {
    u64 r; unsigned u = __float_as_uint(w);
    asm("mov.b64 %0, {%1, %1};" : "=l"(r) : "r"(u));
    return r;
}
__device__ __forceinline__ u64 pack2f(float a, float b) {
    u64 r;
    asm("mov.b64 %0, {%1, %2};" : "=l"(r) : "r"(__float_as_uint(a)), "r"(__float_as_uint(b)));
    return r;
}
__device__ __forceinline__ void fma2(u64& d, u64 a, u64 b) {
    asm("fma.rn.f32x2 %0, %1, %2, %0;" : "+l"(d) : "l"(a), "l"(b));
}
__device__ __forceinline__ float lo32(u64 v) { return __uint_as_float((unsigned)v); }
__device__ __forceinline__ float hi32(u64 v) { return __uint_as_float((unsigned)(v >> 32)); }

__device__ __forceinline__ float fast_tanhf(float x) {
    float e = __expf(2.0f * x);
    return 1.0f - __fdividef(2.0f, e + 1.0f);
}

// One vf eval + inline stage combine.
__device__ __noinline__ void vf_eval(float* sm, float tstage, int tid,
                                     const float* ysSrc, float* kOut,
                                     float hh, float c1, float c2, float c3,
                                     float c4, float c5, float ccur,
                                     float* ysOut) {
    const int j = tid;

    // ---- layer 0: h1 = tanh(ys @ W0^T + b0), K=64 ----
    {
        u64 acc[8];
#pragma unroll
        for (int p = 0; p < 8; p++) acc[p] = 0ull;
        const float4* w4 = (const float4*)(sm + OFF_W0 + j * 68);
        const ulonglong2* a2 = (const ulonglong2*)ysSrc;
#pragma unroll 4
        for (int kk = 0; kk < 16; kk++) {
            float4 w = w4[kk];
            u64 wd0 = pack2(w.x), wd1 = pack2(w.y), wd2 = pack2(w.z), wd3 = pack2(w.w);
#pragma unroll
            for (int p = 0; p < 8; p++) {
                ulonglong2 x0 = a2[p * 32 + kk * 2];
                ulonglong2 x1 = a2[p * 32 + kk * 2 + 1];
                fma2(acc[p], x0.x, wd0);
                fma2(acc[p], x0.y, wd1);
                fma2(acc[p], x1.x, wd2);
                fma2(acc[p], x1.y, wd3);
            }
        }
        float b = sm[OFF_B0 + j];
        u64* h1u = (u64*)(sm + OFF_H1);
#pragma unroll
        for (int p = 0; p < 8; p++) {
            float tl = fast_tanhf(lo32(acc[p]) + b);
            float th = fast_tanhf(hi32(acc[p]) + b);
            h1u[p * 256 + j] = pack2f(tl, th);
        }
    }
    __syncthreads();

    // ---- layer 1: h2 = tanh(h1 @ W1^T + b1), K=256, pipelined LDG.128 ----
    {
        u64 acc[8];
#pragma unroll
        for (int p = 0; p < 8; p++) acc[p] = 0ull;
        const ulonglong2* h2a = (const ulonglong2*)(sm + OFF_H1);
        const float4* wp4 = g_W1P + j;   // element (kk, j) at kk*WID + j

        float4 wc[4], wn[4];
#pragma unroll
        for (int q = 0; q < 4; q++) wc[q] = wp4[q * WID];

#pragma unroll 1
        for (int g = 0; g < 16; g++) {
            // prefetch next group of 4 k-quads (hidden behind this group's math)
            if (g < 15) {
#pragma unroll
                for (int q = 0; q < 4; q++) wn[q] = wp4[(4 * (g + 1) + q) * WID];
            }
#pragma unroll
            for (int q = 0; q < 4; q++) {
                int kk = 4 * g + q;
                u64 wd0 = pack2(wc[q].x), wd1 = pack2(wc[q].y),
                    wd2 = pack2(wc[q].z), wd3 = pack2(wc[q].w);
#pragma unroll
                for (int p = 0; p < 8; p++) {
                    ulonglong2 x0 = h2a[p * 128 + kk * 2];
                    ulonglong2 x1 = h2a[p * 128 + kk * 2 + 1];
                    fma2(acc[p], x0.x, wd0);
                    fma2(acc[p], x0.y, wd1);
                    fma2(acc[p], x1.x, wd2);
                    fma2(acc[p], x1.y, wd3);
                }
            }
#pragma unroll
            for (int q = 0; q < 4; q++) wc[q] = wn[q];
        }
        float b = sm[OFF_B1 + j];
        u64* h2u = (u64*)(sm + OFF_H2);
#pragma unroll
        for (int p = 0; p < 8; p++) {
            float tl = fast_tanhf(lo32(acc[p]) + b);
            float th = fast_tanhf(hi32(acc[p]) + b);
            h2u[p * 256 + j] = pack2f(tl, th);
        }
    }
    __syncthreads();

    // ---- layer 2 + stage combine ----
    {
        const int d = tid & 63;
        const int q = tid >> 6;
        const int p0 = q * 2;
        u64 acc0 = 0ull, acc1 = 0ull;
        const float4* w2p = (const float4*)(sm + OFF_W2 + d * 264);
        const ulonglong2* hv = (const ulonglong2*)(sm + OFF_H2);
#pragma unroll 4
        for (int kk = 0; kk < 64; kk++) {
            float4 w = w2p[kk];
            u64 wd0 = pack2(w.x), wd1 = pack2(w.y), wd2 = pack2(w.z), wd3 = pack2(w.w);
            ulonglong2 xa = hv[p0 * 128 + 2 * kk];
            ulonglong2 xb = hv[p0 * 128 + 2 * kk + 1];
            ulonglong2 ya = hv[(p0 + 1) * 128 + 2 * kk];
            ulonglong2 yb = hv[(p0 + 1) * 128 + 2 * kk + 1];
            fma2(acc0, xa.x, wd0); fma2(acc0, xa.y, wd1);
            fma2(acc0, xb.x, wd2); fma2(acc0, xb.y, wd3);
            fma2(acc1, ya.x, wd0); fma2(acc1, ya.y, wd1);
            fma2(acc1, yb.x, wd2); fma2(acc1, yb.y, wd3);
        }
        float et = __expf(tstage);
        float bv = sm[OFF_B2 + d];
        u64 kv0 = pack2f((lo32(acc0) + bv) * et, (hi32(acc0) + bv) * et);
        u64 kv1 = pack2f((lo32(acc1) + bv) * et, (hi32(acc1) + bv) * et);
        u64* ku = (u64*)kOut;
        ku[p0 * 64 + d] = kv0;
        ku[(p0 + 1) * 64 + d] = kv1;

        // inline combine: ysOut = y + hh*(c1*k1 + ... + c5*k5 + ccur*kcur)
        const u64* k1u = (const u64*)(sm + OFF_K + 0 * 1024);
        const u64* k2u = (const u64*)(sm + OFF_K + 1 * 1024);
        const u64* k3u = (const u64*)(sm + OFF_K + 2 * 1024);
        const u64* k4u = (const u64*)(sm + OFF_K + 3 * 1024);
        const u64* k5u = (const u64*)(sm + OFF_K + 4 * 1024);
        const u64* yu = (const u64*)(sm + OFF_Y);
        u64* yo = (u64*)ysOut;
        u64 C1 = pack2(hh * c1), C2 = pack2(hh * c2), C3 = pack2(hh * c3);
        u64 C4 = pack2(hh * c4), C5 = pack2(hh * c5), CC = pack2(hh * ccur);
        {
            int idx = p0 * 64 + d;
            u64 s = yu[idx];
            fma2(s, C1, k1u[idx]); fma2(s, C2, k2u[idx]); fma2(s, C3, k3u[idx]);
            fma2(s, C4, k4u[idx]); fma2(s, C5, k5u[idx]); fma2(s, CC, kv0);
            yo[idx] = s;
        }
        {
            int idx = (p0 + 1) * 64 + d;
            u64 s = yu[idx];
            fma2(s, C1, k1u[idx]); fma2(s, C2, k2u[idx]); fma2(s, C3, k3u[idx]);
            fma2(s, C4, k4u[idx]); fma2(s, C5, k5u[idx]); fma2(s, CC, kv1);
            yo[idx] = s;
        }
    }
    __syncthreads();
}

__global__ void __launch_bounds__(NT, 1)
node_kernel(const float* __restrict__ ts, const float* __restrict__ y0,
            const float* __restrict__ W0, const float* __restrict__ b0,
            const float* __restrict__ b1, const float* __restrict__ W2,
            const float* __restrict__ b2, float* __restrict__ out) {
    extern __shared__ float sm[];
    const int tid = threadIdx.x;
    const int row0 = blockIdx.x * MT;

    for (int idx = tid; idx < WID * DIM; idx += NT) {
        int j = idx >> 6, d = idx & 63;
        sm[OFF_W0 + j * 68 + d] = W0[idx];
    }
    for (int idx = tid; idx < DIM * WID; idx += NT) {
        int d = idx >> 8, k = idx & 255;
        sm[OFF_W2 + d * 264 + k] = W2[idx];
    }
    sm[OFF_B0 + tid] = b0[tid];
    sm[OFF_B1 + tid] = b1[tid];
    if (tid < DIM) sm[OFF_B2 + tid] = b2[tid];
    for (int idx = tid; idx < 6144; idx += NT) sm[OFF_K + idx] = 0.0f;

    for (int i = tid; i < 512; i += NT) {
        int p = i >> 6, d = i & 63;
        float vlo = y0[(size_t)(row0 + p) * DIM + d];
        float vhi = y0[(size_t)(row0 + p + 8) * DIM + d];
        ((float2*)(sm + OFF_Y))[i] = make_float2(vlo, vhi);
        out[(size_t)(row0 + p) * DIM + d] = vlo;
        out[(size_t)(row0 + p + 8) * DIM + d] = vhi;
    }
    __syncthreads();

    float* yP = sm + OFF_Y;
    float* ysP = sm + OFF_YS;
    float* k1 = sm + OFF_K + 0 * 1024;
    float* k2 = sm + OFF_K + 1 * 1024;
    float* k3 = sm + OFF_K + 2 * 1024;
    float* k4 = sm + OFF_K + 3 * 1024;
    float* k5 = sm + OFF_K + 4 * 1024;
    float* k6 = sm + OFF_K + 5 * 1024;

    const float A21 = 0.2f;
    const float A31 = (float)(3.0 / 40.0), A32 = (float)(9.0 / 40.0);
    const float A41 = (float)(44.0 / 45.0), A42 = (float)(-56.0 / 15.0), A43 = (float)(32.0 / 9.0);
    const float A51 = (float)(19372.0 / 6561.0), A52 = (float)(-25360.0 / 2187.0),
                A53 = (float)(64448.0 / 6561.0), A54 = (float)(-212.0 / 729.0);
    const float A61 = (float)(9017.0 / 3168.0), A62 = (float)(-355.0 / 33.0),
                A63 = (float)(46732.0 / 5247.0), A64 = (float)(49.0 / 176.0),
                A65 = (float)(-5103.0 / 18656.0);
    const float B1 = (float)(35.0 / 384.0), B3 = (float)(500.0 / 1113.0),
                B4 = (float)(125.0 / 192.0), B5 = (float)(-2187.0 / 6784.0),
                B6 = (float)(11.0 / 84.0);

    for (int iv = 0; iv < 31; iv++) {
        float t0 = ts[iv];
        float dtf = ts[iv + 1] - t0;
        float hh = dtf * 0.5f;
        float tc = t0;

        for (int sub = 0; sub < 2; sub++) {
            vf_eval(sm, tc, tid, yP, k1,
                    hh, 0.f, 0.f, 0.f, 0.f, 0.f, A21, ysP);
            vf_eval(sm, tc + 0.2f * hh, tid, ysP, k2,
                    hh, A31, 0.f, 0.f, 0.f, 0.f, A32, ysP);
            vf_eval(sm, tc + 0.3f * hh, tid, ysP, k3,
                    hh, A41, A42, 0.f, 0.f, 0.f, A43, ysP);
            vf_eval(sm, tc + 0.8f * hh, tid, ysP, k4,
                    hh, A51, A52, A53, 0.f, 0.f, A54, ysP);
            vf_eval(sm, tc + (float)(8.0 / 9.0) * hh, tid, ysP, k5,
                    hh, A61, A62, A63, A64, 0.f, A65, ysP);
            vf_eval(sm, tc + hh, tid, ysP, k6,
                    hh, B1, 0.f, B3, B4, B5, B6, yP);
            tc += hh;
        }

        for (int i = tid; i < 512; i += NT) {
            int p = i >> 6, d = i & 63;
            float2 v = ((float2*)(sm + OFF_Y))[i];
            size_t base = (size_t)(iv + 1) * BD;
            out[base + (size_t)(row0 + p) * DIM + d] = v.x;
            out[base + (size_t)(row0 + p + 8) * DIM + d] = v.y;
        }
        __syncthreads();
    }
}

extern "C" void kernel_launch(void* const* d_in, const int* in_sizes, int n_in,
                              void* d_out, int out_size) {
    const float* ts = (const float*)d_in[0];
    const float* y0 = (const float*)d_in[1];
    const float* W0 = (const float*)d_in[2];
    const float* b0 = (const float*)d_in[3];
    const float* W1 = (const float*)d_in[4];
    const float* b1 = (const float*)d_in[5];
    const float* W2 = (const float*)d_in[6];
    const float* b2 = (const float*)d_in[7];
    float* out = (float*)d_out;

    cudaFuncSetAttribute(node_kernel, cudaFuncAttributeMaxDynamicSharedMemorySize,
                         SMEM_BYTES);

    pack_w1<<<64, 256>>>(W1);
    node_kernel<<<NBLK, NT, SMEM_BYTES>>>(ts, y0, W0, b0, b1, W2, b2, out);
}

// round 9
// speedup vs baseline: 1.9292x; 1.9292x over previous
#include <cuda_runtime.h>

// NeuralODE dopri5 rollout — tf32 mma.sync (m16n8k8) persistent kernel, v5.
// Per CTA: 16 batch rows, 8 warps, 256 threads. GEMMs on tensor pipe,
// weights fragment-packed in global, activations tf32 in smem.

#define NT 256
#define MT 16
#define NBLK 128
#define DIM 64
#define WID 256
#define BD (2048*64)

#define S64 68      // stride for 64-col arrays  (68 mod 32 == 4 -> conflict-free frags)
#define S256 260    // stride for 256-col arrays (260 mod 32 == 4)

// shared memory layout (float offsets)
#define OFF_B0 0
#define OFF_B1 256
#define OFF_B2 512
#define OFF_Y  576        // f32, 16 x S64  = 1088
#define OFF_YS 1664       // tf32 bits, 16 x S64 = 1088
#define OFF_H1 2752       // tf32 bits, 16 x S256 = 4160
#define OFF_H2 6912       // tf32 bits, 16 x S256 = 4160
#define OFF_K  11072      // f32, 6 x 1088 = 6528
#define SMEM_FLOATS 17600
#define SMEM_BYTES (SMEM_FLOATS * 4)

// fragment-packed weights: [(nt*NKP + kp)*32 + lane] -> {b0(2kp),b1(2kp),b0(2kp+1),b1(2kp+1)}
__device__ float4 g_W0f[32 * 4 * 32];    // 256x64  : 32 ntiles, 4 kpairs
__device__ float4 g_W1f[32 * 16 * 32];   // 256x256 : 32 ntiles, 16 kpairs
__device__ float4 g_W2f[8 * 16 * 32];    // 64x256  : 8 ntiles, 16 kpairs

__device__ __forceinline__ unsigned tf32r(float f) {
    unsigned r;
    asm("cvt.rna.tf32.f32 %0, %1;" : "=r"(r) : "f"(f));
    return r;
}

__device__ __forceinline__ void pack_body(const float* __restrict__ W, float4* dst,
                                          int NIN, int NKP, int t) {
    int lane = t & 31;
    int kp = (t >> 5) % NKP;
    int nt = (t >> 5) / NKP;
    int row = nt * 8 + (lane >> 2);
    int k0 = kp * 16 + (lane & 3);
    float4 v;
    v.x = __uint_as_float(tf32r(W[row * NIN + k0]));
    v.y = __uint_as_float(tf32r(W[row * NIN + k0 + 4]));
    v.z = __uint_as_float(tf32r(W[row * NIN + k0 + 8]));
    v.w = __uint_as_float(tf32r(W[row * NIN + k0 + 12]));
    dst[t] = v;
}

__global__ void pack_w0(const float* __restrict__ W) {
    pack_body(W, g_W0f, 64, 4, blockIdx.x * 256 + threadIdx.x);
}
__global__ void pack_w1(const float* __restrict__ W) {
    pack_body(W, g_W1f, 256, 16, blockIdx.x * 256 + threadIdx.x);
}
__global__ void pack_w2(const float* __restrict__ W) {
    pack_body(W, g_W2f, 256, 16, blockIdx.x * 256 + threadIdx.x);
}

__device__ __forceinline__ void mma8(float c[4], unsigned a0, unsigned a1,
                                     unsigned a2, unsigned a3,
                                     float b0, float b1) {
    asm("mma.sync.aligned.m16n8k8.row.col.f32.tf32.tf32.f32 "
        "{%0,%1,%2,%3},{%4,%5,%6,%7},{%8,%9},{%0,%1,%2,%3};"
        : "+f"(c[0]), "+f"(c[1]), "+f"(c[2]), "+f"(c[3])
        : "r"(a0), "r"(a1), "r"(a2), "r"(a3),
          "r"(__float_as_uint(b0)), "r"(__float_as_uint(b1)));
}

__device__ __forceinline__ float fast_tanhf(float x) {
    float e = __expf(2.0f * x);
    return 1.0f - __fdividef(2.0f, e + 1.0f);
}

// GEMM + tanh epilogue: A (tf32 bits, strideA) @ Wf -> Hout (tf32 bits, S256)
__device__ __forceinline__ void gemm_tanh(const unsigned* __restrict__ As, int sa,
                                          const float4* __restrict__ Bf, int nkp,
                                          const float* __restrict__ bias_s,
                                          unsigned* __restrict__ Hout,
                                          int wid, int gr, int gc) {
    float C[4][4];
#pragma unroll
    for (int q = 0; q < 4; q++)
#pragma unroll
        for (int e = 0; e < 4; e++) C[q][e] = 0.0f;

#pragma unroll 2
    for (int kp = 0; kp < nkp; kp++) {
        int k0 = kp * 16;
        unsigned a00 = As[gr * sa + k0 + gc];
        unsigned a01 = As[(gr + 8) * sa + k0 + gc];
        unsigned a02 = As[gr * sa + k0 + gc + 4];
        unsigned a03 = As[(gr + 8) * sa + k0 + gc + 4];
        unsigned a10 = As[gr * sa + k0 + 8 + gc];
        unsigned a11 = As[(gr + 8) * sa + k0 + 8 + gc];
        unsigned a12 = As[gr * sa + k0 + 8 + gc + 4];
        unsigned a13 = As[(gr + 8) * sa + k0 + 8 + gc + 4];
#pragma unroll
        for (int q = 0; q < 4; q++) {
            float4 bv = Bf[((wid * 4 + q) * nkp + kp) * 32 + (gr * 4 + gc)];
            mma8(C[q], a00, a01, a02, a03, bv.x, bv.y);
            mma8(C[q], a10, a11, a12, a13, bv.z, bv.w);
        }
    }
#pragma unroll
    for (int q = 0; q < 4; q++) {
        int col0 = (wid * 4 + q) * 8 + 2 * gc;
        float bb0 = bias_s[col0];
        float bb1 = bias_s[col0 + 1];
        uint2 v0, v1;
        v0.x = tf32r(fast_tanhf(C[q][0] + bb0));
        v0.y = tf32r(fast_tanhf(C[q][1] + bb1));
        v1.x = tf32r(fast_tanhf(C[q][2] + bb0));
        v1.y = tf32r(fast_tanhf(C[q][3] + bb1));
        *(uint2*)(Hout + gr * S256 + col0) = v0;
        *(uint2*)(Hout + (gr + 8) * S256 + col0) = v1;
    }
}

// One vf eval (3 GEMMs) + inline stage combine.
__device__ __noinline__ void vf_eval(float* sm, float tstage, float hh,
                                     float c1, float c2, float c3, float c4,
                                     float c5, float ccur, int final_, int kslot,
                                     int wid, int lane) {
    const int gr = lane >> 2;
    const int gc = lane & 3;
    unsigned* sYs = (unsigned*)(sm + OFF_YS);
    unsigned* sH1 = (unsigned*)(sm + OFF_H1);
    unsigned* sH2 = (unsigned*)(sm + OFF_H2);

    // L0: ys @ W0^T -> H1
    gemm_tanh(sYs, S64, g_W0f, 4, sm + OFF_B0, sH1, wid, gr, gc);
    __syncthreads();
    // L1: H1 @ W1^T -> H2
    gemm_tanh(sH1, S256, g_W1f, 16, sm + OFF_B1, sH2, wid, gr, gc);
    __syncthreads();

    // L2: H2 @ W2^T -> k, + combine
    {
        float C[4] = {0.f, 0.f, 0.f, 0.f};
#pragma unroll 4
        for (int kp = 0; kp < 16; kp++) {
            int k0 = kp * 16;
            unsigned a00 = sH2[gr * S256 + k0 + gc];
            unsigned a01 = sH2[(gr + 8) * S256 + k0 + gc];
            unsigned a02 = sH2[gr * S256 + k0 + gc + 4];
            unsigned a03 = sH2[(gr + 8) * S256 + k0 + gc + 4];
            unsigned a10 = sH2[gr * S256 + k0 + 8 + gc];
            unsigned a11 = sH2[(gr + 8) * S256 + k0 + 8 + gc];
            unsigned a12 = sH2[gr * S256 + k0 + 8 + gc + 4];
            unsigned a13 = sH2[(gr + 8) * S256 + k0 + 8 + gc + 4];
            float4 bv = g_W2f[(wid * 16 + kp) * 32 + lane];
            mma8(C, a00, a01, a02, a03, bv.x, bv.y);
            mma8(C, a10, a11, a12, a13, bv.z, bv.w);
        }
        float et = __expf(tstage);
        int col0 = wid * 8 + 2 * gc;
        float* sY = sm + OFF_Y;
        float* sK = sm + OFF_K;
        float* kout = sK + kslot * 1088;
        const float* k1p = sK;
        const float* k2p = sK + 1088;
        const float* k3p = sK + 2 * 1088;
        const float* k4p = sK + 3 * 1088;
        const float* k5p = sK + 4 * 1088;
#pragma unroll
        for (int e = 0; e < 4; e++) {
            int row = gr + ((e >> 1) << 3);
            int col = col0 + (e & 1);
            int idx = row * S64 + col;
            float kv = (C[e] + sm[OFF_B2 + col]) * et;
            kout[idx] = kv;
            float acc = c1 * k1p[idx] + c2 * k2p[idx] + c3 * k3p[idx]
                      + c4 * k4p[idx] + c5 * k5p[idx] + ccur * kv;
            acc = fmaf(hh, acc, sY[idx]);
            if (final_) sY[idx] = acc;
            ((unsigned*)(sm + OFF_YS))[idx] = tf32r(acc);
        }
    }
    __syncthreads();
}

__global__ void __launch_bounds__(NT, 1)
node_kernel(const float* __restrict__ ts, const float* __restrict__ y0,
            const float* __restrict__ b0, const float* __restrict__ b1,
            const float* __restrict__ b2, float* __restrict__ out) {
    extern __shared__ float sm[];
    const int tid = threadIdx.x;
    const int wid = tid >> 5;
    const int lane = tid & 31;
    const int row0 = blockIdx.x * MT;

    sm[OFF_B0 + tid] = b0[tid];
    sm[OFF_B1 + tid] = b1[tid];
    if (tid < DIM) sm[OFF_B2 + tid] = b2[tid];
    for (int i = tid; i < 6 * 1088; i += NT) sm[OFF_K + i] = 0.0f;

    // load y0 (f32 + tf32 copies), write output slab t=0
    for (int i = tid; i < MT * DIM; i += NT) {
        int r = i >> 6, c = i & 63;
        float v = y0[(size_t)(row0 + r) * DIM + c];
        sm[OFF_Y + r * S64 + c] = v;
        ((unsigned*)(sm + OFF_YS))[r * S64 + c] = tf32r(v);
        out[(size_t)(row0 + r) * DIM + c] = v;
    }
    __syncthreads();

    const float A21 = 0.2f;
    const float A31 = (float)(3.0 / 40.0), A32 = (float)(9.0 / 40.0);
    const float A41 = (float)(44.0 / 45.0), A42 = (float)(-56.0 / 15.0), A43 = (float)(32.0 / 9.0);
    const float A51 = (float)(19372.0 / 6561.0), A52 = (float)(-25360.0 / 2187.0),
                A53 = (float)(64448.0 / 6561.0), A54 = (float)(-212.0 / 729.0);
    const float A61 = (float)(9017.0 / 3168.0), A62 = (float)(-355.0 / 33.0),
                A63 = (float)(46732.0 / 5247.0), A64 = (float)(49.0 / 176.0),
                A65 = (float)(-5103.0 / 18656.0);
    const float B1 = (float)(35.0 / 384.0), B3 = (float)(500.0 / 1113.0),
                B4 = (float)(125.0 / 192.0), B5 = (float)(-2187.0 / 6784.0),
                B6 = (float)(11.0 / 84.0);

    for (int iv = 0; iv < 31; iv++) {
        float t0 = ts[iv];
        float dtf = ts[iv + 1] - t0;
        float hh = dtf * 0.5f;
        float tc = t0;

        for (int sub = 0; sub < 2; sub++) {
            vf_eval(sm, tc, hh,
                    0.f, 0.f, 0.f, 0.f, 0.f, A21, 0, 0, wid, lane);
            vf_eval(sm, tc + 0.2f * hh, hh,
                    A31, 0.f, 0.f, 0.f, 0.f, A32, 0, 1, wid, lane);
            vf_eval(sm, tc + 0.3f * hh, hh,
                    A41, A42, 0.f, 0.f, 0.f, A43, 0, 2, wid, lane);
            vf_eval(sm, tc + 0.8f * hh, hh,
                    A51, A52, A53, 0.f, 0.f, A54, 0, 3, wid, lane);
            vf_eval(sm, tc + (float)(8.0 / 9.0) * hh, hh,
                    A61, A62, A63, A64, 0.f, A65, 0, 4, wid, lane);
            vf_eval(sm, tc + hh, hh,
                    B1, 0.f, B3, B4, B5, B6, 1, 5, wid, lane);
            tc += hh;
        }

        // write output slab t = iv+1
        for (int i = tid; i < MT * DIM; i += NT) {
            int r = i >> 6, c = i & 63;
            out[(size_t)(iv + 1) * BD + (size_t)(row0 + r) * DIM + c] =
                sm[OFF_Y + r * S64 + c];
        }
        __syncthreads();
    }
}

extern "C" void kernel_launch(void* const* d_in, const int* in_sizes, int n_in,
                              void* d_out, int out_size) {
    const float* ts = (const float*)d_in[0];
    const float* y0 = (const float*)d_in[1];
    const float* W0 = (const float*)d_in[2];
    const float* b0 = (const float*)d_in[3];
    const float* W1 = (const float*)d_in[4];
    const float* b1 = (const float*)d_in[5];
    const float* W2 = (const float*)d_in[6];
    const float* b2 = (const float*)d_in[7];
    float* out = (float*)d_out;

    cudaFuncSetAttribute(node_kernel, cudaFuncAttributeMaxDynamicSharedMemorySize,
                         SMEM_BYTES);

    pack_w0<<<16, 256>>>(W0);   // 32 nt * 4 kp * 32 lanes = 4096
    pack_w1<<<64, 256>>>(W1);   // 32 * 16 * 32 = 16384
    pack_w2<<<16, 256>>>(W2);   // 8 * 16 * 32 = 4096
    node_kernel<<<NBLK, NT, SMEM_BYTES>>>(ts, y0, b0, b1, b2, out);
}